// round 6
// baseline (speedup 1.0000x reference)
#include <cuda_runtime.h>
#include <math.h>

// Problem constants
#define BB   4
#define HH   64
#define WW   64
#define MTOT (BB*HH*WW)      // 16384 pixels
#define CC   256             // coarse / fine channels
#define CF2  512             // concat channels
#define NOM  216             // G*3*K = 8*27
#define KIM  4608            // 9*512 im2col K
#define KDCN 2304            // 9*256
#define GRP  8
#define CG   32              // channels per group

// ---------------- scratch (static device globals; no allocation) -------------
__device__ float g_coarse_up[MTOT*CC];        // 16.8 MB
__device__ float g_pool_part[64*CC];
__device__ float g_attn_p1[BB*CC];            // 1 + sigmoid(attn)
__device__ float g_fine_cal[MTOT*CC];         // 16.8 MB
__device__ float g_align[MTOT*CF2];           // 33.6 MB
__device__ float g_om[MTOT*NOM];              // 14.2 MB
__device__ float g_sampled[(size_t)MTOT*KDCN];// 151 MB

// ---------------- bilinear upsample (half-pixel, edge clamp) ------------------
__global__ void upsample_kernel(const float* __restrict__ coarse) {
    int idx = blockIdx.x * blockDim.x + threadIdx.x;   // [0, 4*64*64*64)
    if (idx >= BB*HH*WW*(CC/4)) return;
    int c4 = idx & 63;
    int x  = (idx >> 6) & 63;
    int y  = (idx >> 12) & 63;
    int b  = idx >> 18;

    float syf = y * 0.5f - 0.25f;
    float sxf = x * 0.5f - 0.25f;
    float y0f = floorf(syf), x0f = floorf(sxf);
    float wy = syf - y0f, wx = sxf - x0f;
    int y0 = max(0, min(31, (int)y0f));
    int y1 = max(0, min(31, (int)y0f + 1));
    int x0 = max(0, min(31, (int)x0f));
    int x1 = max(0, min(31, (int)x0f + 1));

    const float4* src = (const float4*)coarse;
    int base = ((b * 32) * 32) * 64;   // in float4 units per row plane
    float4 v00 = src[base + (y0 * 32 + x0) * 64 + c4];
    float4 v01 = src[base + (y0 * 32 + x1) * 64 + c4];
    float4 v10 = src[base + (y1 * 32 + x0) * 64 + c4];
    float4 v11 = src[base + (y1 * 32 + x1) * 64 + c4];

    float4 r;
    r.x = (v00.x*(1-wx)+v01.x*wx)*(1-wy) + (v10.x*(1-wx)+v11.x*wx)*wy;
    r.y = (v00.y*(1-wx)+v01.y*wx)*(1-wy) + (v10.y*(1-wx)+v11.y*wx)*wy;
    r.z = (v00.z*(1-wx)+v01.z*wx)*(1-wy) + (v10.z*(1-wx)+v11.z*wx)*wy;
    r.w = (v00.w*(1-wx)+v01.w*wx)*(1-wy) + (v10.w*(1-wx)+v11.w*wx)*wy;

    ((float4*)g_coarse_up)[((b*64 + y)*64 + x)*64 + c4] = r;
}

// ---------------- global mean pool: partial sums --------------------------------
__global__ void pool_part_kernel(const float* __restrict__ fine) {
    int bx = blockIdx.x;          // 64 blocks: b = bx>>4, spatial chunk = bx&15
    int b = bx >> 4, t = bx & 15;
    int c = threadIdx.x;
    float acc = 0.f;
    const float* p = fine + ((size_t)(b << 12) + t * 256) * CC + c;
    for (int s = 0; s < 256; s++) acc += p[(size_t)s * CC];
    g_pool_part[bx * CC + c] = acc;
}

// ---------------- attention: reduce partials, 1x1 conv, sigmoid+1 ----------------
__global__ void attn_kernel(const float* __restrict__ w_att) {
    __shared__ float ps[CC];
    int b = blockIdx.x, c = threadIdx.x;
    float acc = 0.f;
    for (int t = 0; t < 16; t++) acc += g_pool_part[(b * 16 + t) * CC + c];
    ps[c] = acc * (1.0f / 4096.0f);
    __syncthreads();
    float logit = 0.f;
    for (int k = 0; k < CC; k++) logit = fmaf(ps[k], w_att[k * CC + c], logit);
    g_attn_p1[b * CC + c] = 1.0f + 1.0f / (1.0f + expf(-logit));
}

// ---------------- generic tiled SGEMM with fused A-loaders / epilogues ----------
// AMODE: 0 plain A, 1 fine*(attn+1), 2 concat(fine_cal, 2*coarse_up), 3 im2col(align)
// EPI:   0 none, 1 +bias, 2 relu(+bias)+epi_add
// Software-pipelined: next k-tile's global loads are issued into registers
// BEFORE the current tile's FMA block, hiding load latency under compute.
#define Bb 128
#define Bn 128
#define Bk 16

template<int AMODE>
__device__ __forceinline__ float loadA(const float* __restrict__ A,
                                       const float* __restrict__ aux0,
                                       const float* __restrict__ aux1,
                                       int m, int k, int K) {
    if (AMODE == 0) return A[(size_t)m * K + k];
    if (AMODE == 1) return aux0[m * CC + k] * aux1[((m >> 12) << 8) + k];
    if (AMODE == 2) return (k < CC) ? aux0[m * CC + k]
                                    : 2.0f * aux1[m * CC + (k - CC)];
    // AMODE == 3 : im2col over g_align [B,H,W,512], SAME zero pad
    {
        int r = k >> 9;            // 0..8  (tap)
        int c = k & 511;
        int ky = r / 3 - 1, kx = r % 3 - 1;
        int b = m >> 12, y = (m >> 6) & 63, x = m & 63;
        int yy = y + ky, xx = x + kx;
        if ((unsigned)yy < 64u && (unsigned)xx < 64u)
            return aux0[((((b << 6) + yy) << 6) + xx) * CF2 + c];
        return 0.f;
    }
}

template<int AMODE, int EPI>
__global__ void __launch_bounds__(256)
gemm_kernel(const float* __restrict__ A, const float* __restrict__ B,
            float* __restrict__ C, int M, int N, int K,
            const float* __restrict__ aux0, const float* __restrict__ aux1,
            const float* __restrict__ bias, const float* __restrict__ epi_add) {
    __shared__ float As[Bk][Bb + 4];
    __shared__ float Bs[Bk][Bn];

    int tid = threadIdx.x;
    int tx = tid & 15, ty = tid >> 4;
    int m0 = blockIdx.y * Bb;
    int n0 = blockIdx.x * Bn;

    float acc[8][8];
#pragma unroll
    for (int i = 0; i < 8; i++)
#pragma unroll
        for (int j = 0; j < 8; j++) acc[i][j] = 0.f;

    int a_kk = tid & 15;          // A loader: fixed k lane per thread
    int a_mrow = tid >> 4;
    int b_nn = tid & 127;         // B loader: fixed n lane per thread
    int b_krow = tid >> 7;

    float pa[8], pb[8];           // prefetch registers

    // ---- prologue: fetch tile 0 ----
#pragma unroll
    for (int t = 0; t < 8; t++)
        pa[t] = loadA<AMODE>(A, aux0, aux1, m0 + a_mrow + t * 16, a_kk, K);
#pragma unroll
    for (int t = 0; t < 8; t++) {
        int n = n0 + b_nn;
        pb[t] = (n < N) ? B[(size_t)(b_krow + t * 2) * N + n] : 0.f;
    }
#pragma unroll
    for (int t = 0; t < 8; t++) As[a_kk][a_mrow + t * 16] = pa[t];
#pragma unroll
    for (int t = 0; t < 8; t++) Bs[b_krow + t * 2][b_nn] = pb[t];
    __syncthreads();

    for (int k0 = 0; k0 < K; k0 += Bk) {
        bool has_next = (k0 + Bk) < K;
        // ---- issue next tile's global loads early (latency hidden by FMAs) ----
        if (has_next) {
            int kn = k0 + Bk;
#pragma unroll
            for (int t = 0; t < 8; t++)
                pa[t] = loadA<AMODE>(A, aux0, aux1, m0 + a_mrow + t * 16, kn + a_kk, K);
#pragma unroll
            for (int t = 0; t < 8; t++) {
                int n = n0 + b_nn;
                pb[t] = (n < N) ? B[(size_t)(kn + b_krow + t * 2) * N + n] : 0.f;
            }
        }

        // ---- compute on current smem tile ----
#pragma unroll
        for (int kk = 0; kk < Bk; kk++) {
            float4 a0 = *(const float4*)&As[kk][ty * 8];
            float4 a1 = *(const float4*)&As[kk][ty * 8 + 4];
            float4 b0 = *(const float4*)&Bs[kk][tx * 8];
            float4 b1 = *(const float4*)&Bs[kk][tx * 8 + 4];
            float rA[8] = {a0.x, a0.y, a0.z, a0.w, a1.x, a1.y, a1.z, a1.w};
            float rB[8] = {b0.x, b0.y, b0.z, b0.w, b1.x, b1.y, b1.z, b1.w};
#pragma unroll
            for (int i = 0; i < 8; i++)
#pragma unroll
                for (int j = 0; j < 8; j++)
                    acc[i][j] = fmaf(rA[i], rB[j], acc[i][j]);
        }
        __syncthreads();          // all threads done reading smem

        if (has_next) {
#pragma unroll
            for (int t = 0; t < 8; t++) As[a_kk][a_mrow + t * 16] = pa[t];
#pragma unroll
            for (int t = 0; t < 8; t++) Bs[b_krow + t * 2][b_nn] = pb[t];
            __syncthreads();      // smem tile ready for next iteration
        }
    }

#pragma unroll
    for (int i = 0; i < 8; i++) {
        int m = m0 + ty * 8 + i;
#pragma unroll
        for (int j = 0; j < 8; j++) {
            int n = n0 + tx * 8 + j;
            if (n < N) {
                float v = acc[i][j];
                if (EPI == 1) v += bias[n];
                if (EPI == 2) v = fmaxf(v + bias[n], 0.f) + epi_add[(size_t)m * N + n];
                C[(size_t)m * N + n] = v;
            }
        }
    }
}

// ---------------- deformable bilinear sampling ------------------------------------
// thread -> (m, k, g); writes 32 contiguous channels of g_sampled[m][k][g*32..]
__global__ void sample_kernel() {
    int idx = blockIdx.x * blockDim.x + threadIdx.x;   // [0, 16384*72)
    if (idx >= MTOT * 9 * GRP) return;
    int g  = idx & 7;
    int mk = idx >> 3;
    int k  = mk % 9;
    int m  = mk / 9;
    int b = m >> 12, y = (m >> 6) & 63, x = m & 63;

    const float* omp = g_om + (size_t)m * NOM;
    float dy = omp[g * 18 + k * 2];
    float dx = omp[g * 18 + k * 2 + 1];
    float mask = 1.0f / (1.0f + expf(-omp[144 + g * 9 + k]));

    float sy = (float)y + (float)(k / 3 - 1) + dy;
    float sx = (float)x + (float)(k % 3 - 1) + dx;
    float y0f = floorf(sy), x0f = floorf(sx);
    float wy = sy - y0f, wx = sx - x0f;

    float vy0 = (y0f >= 0.f && y0f <= 63.f) ? 1.f : 0.f;
    float vy1 = (y0f + 1.f >= 0.f && y0f + 1.f <= 63.f) ? 1.f : 0.f;
    float vx0 = (x0f >= 0.f && x0f <= 63.f) ? 1.f : 0.f;
    float vx1 = (x0f + 1.f >= 0.f && x0f + 1.f <= 63.f) ? 1.f : 0.f;

    int yc0 = (int)fminf(fmaxf(y0f, 0.f), 63.f);
    int yc1 = (int)fminf(fmaxf(y0f + 1.f, 0.f), 63.f);
    int xc0 = (int)fminf(fmaxf(x0f, 0.f), 63.f);
    int xc1 = (int)fminf(fmaxf(x0f + 1.f, 0.f), 63.f);

    float w00 = (1 - wy) * (1 - wx) * vy0 * vx0 * mask;
    float w01 = (1 - wy) * wx       * vy0 * vx1 * mask;
    float w10 = wy       * (1 - wx) * vy1 * vx0 * mask;
    float w11 = wy       * wx       * vy1 * vx1 * mask;

    int plane = (b << 12);
    const float4* p00 = (const float4*)(g_coarse_up + ((plane + (yc0 << 6) + xc0) * CC) + g * CG);
    const float4* p01 = (const float4*)(g_coarse_up + ((plane + (yc0 << 6) + xc1) * CC) + g * CG);
    const float4* p10 = (const float4*)(g_coarse_up + ((plane + (yc1 << 6) + xc0) * CC) + g * CG);
    const float4* p11 = (const float4*)(g_coarse_up + ((plane + (yc1 << 6) + xc1) * CC) + g * CG);

    float4* dst = (float4*)(g_sampled + (size_t)(m * 9 + k) * CC + g * CG);
#pragma unroll
    for (int i = 0; i < 8; i++) {
        float4 a = p00[i], bb = p01[i], c = p10[i], d = p11[i];
        float4 r;
        r.x = w00*a.x + w01*bb.x + w10*c.x + w11*d.x;
        r.y = w00*a.y + w01*bb.y + w10*c.y + w11*d.y;
        r.z = w00*a.z + w01*bb.z + w10*c.z + w11*d.z;
        r.w = w00*a.w + w01*bb.w + w10*c.w + w11*d.w;
        dst[i] = r;
    }
}

// ---------------- launch --------------------------------------------------------
extern "C" void kernel_launch(void* const* d_in, const int* in_sizes, int n_in,
                              void* d_out, int out_size) {
    const float* coarse = (const float*)d_in[0];
    const float* fine   = (const float*)d_in[1];
    const float* w_att  = (const float*)d_in[2];
    const float* w_sel  = (const float*)d_in[3];
    const float* w_off  = (const float*)d_in[4];
    const float* w_om   = (const float*)d_in[5];
    const float* b_om   = (const float*)d_in[6];
    const float* w_dcn  = (const float*)d_in[7];
    const float* b_dcn  = (const float*)d_in[8];
    float* out = (float*)d_out;

    float *cu, *fcal, *alg, *om, *samp, *attn;
    cudaGetSymbolAddress((void**)&cu,   g_coarse_up);
    cudaGetSymbolAddress((void**)&fcal, g_fine_cal);
    cudaGetSymbolAddress((void**)&alg,  g_align);
    cudaGetSymbolAddress((void**)&om,   g_om);
    cudaGetSymbolAddress((void**)&samp, g_sampled);
    cudaGetSymbolAddress((void**)&attn, g_attn_p1);

    upsample_kernel<<<(BB*HH*WW*CC/4 + 255)/256, 256>>>(coarse);
    pool_part_kernel<<<64, 256>>>(fine);
    attn_kernel<<<BB, 256>>>(w_att);

    // fine_cal = (fine * (attn+1)) @ w_sel
    gemm_kernel<1,0><<<dim3(2,128), 256>>>(nullptr, w_sel, fcal,
        MTOT, CC, CC, fine, attn, nullptr, nullptr);

    // align = concat(fine_cal, 2*coarse_up) @ w_off
    gemm_kernel<2,0><<<dim3(4,128), 256>>>(nullptr, w_off, alg,
        MTOT, CF2, CF2, fcal, cu, nullptr, nullptr);

    // om = conv3x3(align, w_om) + b_om   (im2col-fused)
    gemm_kernel<3,1><<<dim3(2,128), 256>>>(nullptr, w_om, om,
        MTOT, NOM, KIM, alg, nullptr, b_om, nullptr);

    // deformable sampling -> g_sampled [16384, 9*256]
    sample_kernel<<<(MTOT*9*GRP + 255)/256, 256>>>();

    // out = relu(sampled @ w_dcn + b_dcn) + fine_cal
    gemm_kernel<0,2><<<dim3(2,128), 256>>>(samp, w_dcn, out,
        MTOT, CC, KDCN, nullptr, nullptr, b_dcn, fcal);
}

// round 8
// speedup vs baseline: 1.1641x; 1.1641x over previous
#include <cuda_runtime.h>
#include <math.h>

// Problem constants
#define BB   4
#define HH   64
#define WW   64
#define MTOT (BB*HH*WW)      // 16384 pixels
#define CC   256             // coarse / fine channels
#define CF2  512             // concat channels
#define NOM  216             // G*3*K = 8*27
#define KIM  4608            // 9*512 im2col K
#define KDCN 2304            // 9*256
#define GRP  8
#define CG   32              // channels per group

// ---------------- scratch (static device globals; no allocation) -------------
__device__ float g_coarse_up[MTOT*CC];        // 16.8 MB
__device__ float g_pool_part[64*CC];
__device__ float g_attn_p1[BB*CC];            // 1 + sigmoid(attn)
__device__ float g_fine_cal[MTOT*CC];         // 16.8 MB
__device__ float g_align[MTOT*CF2];           // 33.6 MB
__device__ float g_om[MTOT*NOM];              // 14.2 MB
__device__ float g_sampled[(size_t)MTOT*KDCN];// 151 MB

// ---------------- bilinear upsample (half-pixel, edge clamp) ------------------
__global__ void upsample_kernel(const float* __restrict__ coarse) {
    int idx = blockIdx.x * blockDim.x + threadIdx.x;   // [0, 4*64*64*64)
    if (idx >= BB*HH*WW*(CC/4)) return;
    int c4 = idx & 63;
    int x  = (idx >> 6) & 63;
    int y  = (idx >> 12) & 63;
    int b  = idx >> 18;

    float syf = y * 0.5f - 0.25f;
    float sxf = x * 0.5f - 0.25f;
    float y0f = floorf(syf), x0f = floorf(sxf);
    float wy = syf - y0f, wx = sxf - x0f;
    int y0 = max(0, min(31, (int)y0f));
    int y1 = max(0, min(31, (int)y0f + 1));
    int x0 = max(0, min(31, (int)x0f));
    int x1 = max(0, min(31, (int)x0f + 1));

    const float4* src = (const float4*)coarse;
    int base = ((b * 32) * 32) * 64;   // in float4 units per row plane
    float4 v00 = src[base + (y0 * 32 + x0) * 64 + c4];
    float4 v01 = src[base + (y0 * 32 + x1) * 64 + c4];
    float4 v10 = src[base + (y1 * 32 + x0) * 64 + c4];
    float4 v11 = src[base + (y1 * 32 + x1) * 64 + c4];

    float4 r;
    r.x = (v00.x*(1-wx)+v01.x*wx)*(1-wy) + (v10.x*(1-wx)+v11.x*wx)*wy;
    r.y = (v00.y*(1-wx)+v01.y*wx)*(1-wy) + (v10.y*(1-wx)+v11.y*wx)*wy;
    r.z = (v00.z*(1-wx)+v01.z*wx)*(1-wy) + (v10.z*(1-wx)+v11.z*wx)*wy;
    r.w = (v00.w*(1-wx)+v01.w*wx)*(1-wy) + (v10.w*(1-wx)+v11.w*wx)*wy;

    ((float4*)g_coarse_up)[((b*64 + y)*64 + x)*64 + c4] = r;
}

// ---------------- global mean pool: partial sums --------------------------------
__global__ void pool_part_kernel(const float* __restrict__ fine) {
    int bx = blockIdx.x;          // 64 blocks: b = bx>>4, spatial chunk = bx&15
    int b = bx >> 4, t = bx & 15;
    int c = threadIdx.x;
    float acc = 0.f;
    const float* p = fine + ((size_t)(b << 12) + t * 256) * CC + c;
    for (int s = 0; s < 256; s++) acc += p[(size_t)s * CC];
    g_pool_part[bx * CC + c] = acc;
}

// ---------------- attention: reduce partials, 1x1 conv, sigmoid+1 ----------------
__global__ void attn_kernel(const float* __restrict__ w_att) {
    __shared__ float ps[CC];
    int b = blockIdx.x, c = threadIdx.x;
    float acc = 0.f;
    for (int t = 0; t < 16; t++) acc += g_pool_part[(b * 16 + t) * CC + c];
    ps[c] = acc * (1.0f / 4096.0f);
    __syncthreads();
    float logit = 0.f;
    for (int k = 0; k < CC; k++) logit = fmaf(ps[k], w_att[k * CC + c], logit);
    g_attn_p1[b * CC + c] = 1.0f + 1.0f / (1.0f + expf(-logit));
}

// ---------------- generic tiled SGEMM with fused A-loaders / epilogues ----------
// AMODE: 0 plain A, 1 fine*(attn+1), 2 concat(fine_cal, 2*coarse_up), 3 im2col(align)
// EPI:   0 none, 1 +bias, 2 relu(+bias)+epi_add
// Double-buffered smem (1 sync/iter) + register prefetch of next global tile
// + fragment double-buffering over kk (hides LDS latency under FMAs).
#define Bb 128
#define Bn 128
#define Bk 16

template<int AMODE>
__device__ __forceinline__ float loadA(const float* __restrict__ A,
                                       const float* __restrict__ aux0,
                                       const float* __restrict__ aux1,
                                       int m, int k, int K) {
    if (AMODE == 0) return A[(size_t)m * K + k];
    if (AMODE == 1) return aux0[m * CC + k] * aux1[((m >> 12) << 8) + k];
    if (AMODE == 2) return (k < CC) ? aux0[m * CC + k]
                                    : 2.0f * aux1[m * CC + (k - CC)];
    // AMODE == 3 : im2col over g_align [B,H,W,512], SAME zero pad
    {
        int r = k >> 9;            // 0..8  (tap)
        int c = k & 511;
        int ky = r / 3 - 1, kx = r % 3 - 1;
        int b = m >> 12, y = (m >> 6) & 63, x = m & 63;
        int yy = y + ky, xx = x + kx;
        if ((unsigned)yy < 64u && (unsigned)xx < 64u)
            return aux0[((((b << 6) + yy) << 6) + xx) * CF2 + c];
        return 0.f;
    }
}

template<int AMODE, int EPI>
__global__ void __launch_bounds__(256)
gemm_kernel(const float* __restrict__ A, const float* __restrict__ B,
            float* __restrict__ C, int M, int N, int K,
            const float* __restrict__ aux0, const float* __restrict__ aux1,
            const float* __restrict__ bias, const float* __restrict__ epi_add) {
    __shared__ float As[2][Bk][Bb + 4];
    __shared__ float Bs[2][Bk][Bn];

    int tid = threadIdx.x;
    int tx = tid & 15, ty = tid >> 4;
    int m0 = blockIdx.y * Bb;
    int n0 = blockIdx.x * Bn;

    float acc[8][8];
#pragma unroll
    for (int i = 0; i < 8; i++)
#pragma unroll
        for (int j = 0; j < 8; j++) acc[i][j] = 0.f;

    int a_kk = tid & 15;          // A loader: fixed k lane per thread
    int a_mrow = tid >> 4;
    int b_nn = tid & 127;         // B loader: fixed n lane per thread
    int b_krow = tid >> 7;

    float pa[8], pb[8];           // global prefetch registers

    // ---- prologue: fetch tile 0 into buffer 0 ----
#pragma unroll
    for (int t = 0; t < 8; t++)
        pa[t] = loadA<AMODE>(A, aux0, aux1, m0 + a_mrow + t * 16, a_kk, K);
#pragma unroll
    for (int t = 0; t < 8; t++) {
        int n = n0 + b_nn;
        pb[t] = (n < N) ? B[(size_t)(b_krow + t * 2) * N + n] : 0.f;
    }
#pragma unroll
    for (int t = 0; t < 8; t++) As[0][a_kk][a_mrow + t * 16] = pa[t];
#pragma unroll
    for (int t = 0; t < 8; t++) Bs[0][b_krow + t * 2][b_nn] = pb[t];
    __syncthreads();

    int buf = 0;
    for (int k0 = 0; k0 < K; k0 += Bk, buf ^= 1) {
        bool has_next = (k0 + Bk) < K;
        // ---- issue next tile's global loads early ----
        if (has_next) {
            int kn = k0 + Bk;
#pragma unroll
            for (int t = 0; t < 8; t++)
                pa[t] = loadA<AMODE>(A, aux0, aux1, m0 + a_mrow + t * 16, kn + a_kk, K);
#pragma unroll
            for (int t = 0; t < 8; t++) {
                int n = n0 + b_nn;
                pb[t] = (n < N) ? B[(size_t)(kn + b_krow + t * 2) * N + n] : 0.f;
            }
        }

        // ---- compute on current buffer, fragments double-buffered over kk ----
        float rA[2][8], rB[2][8];
        {
            float4 a0 = *(const float4*)&As[buf][0][ty * 8];
            float4 a1 = *(const float4*)&As[buf][0][ty * 8 + 4];
            float4 b0 = *(const float4*)&Bs[buf][0][tx * 8];
            float4 b1 = *(const float4*)&Bs[buf][0][tx * 8 + 4];
            rA[0][0]=a0.x; rA[0][1]=a0.y; rA[0][2]=a0.z; rA[0][3]=a0.w;
            rA[0][4]=a1.x; rA[0][5]=a1.y; rA[0][6]=a1.z; rA[0][7]=a1.w;
            rB[0][0]=b0.x; rB[0][1]=b0.y; rB[0][2]=b0.z; rB[0][3]=b0.w;
            rB[0][4]=b1.x; rB[0][5]=b1.y; rB[0][6]=b1.z; rB[0][7]=b1.w;
        }
#pragma unroll
        for (int kk = 0; kk < Bk; kk++) {
            int cur = kk & 1, nxt = cur ^ 1;
            if (kk < Bk - 1) {
                float4 a0 = *(const float4*)&As[buf][kk + 1][ty * 8];
                float4 a1 = *(const float4*)&As[buf][kk + 1][ty * 8 + 4];
                float4 b0 = *(const float4*)&Bs[buf][kk + 1][tx * 8];
                float4 b1 = *(const float4*)&Bs[buf][kk + 1][tx * 8 + 4];
                rA[nxt][0]=a0.x; rA[nxt][1]=a0.y; rA[nxt][2]=a0.z; rA[nxt][3]=a0.w;
                rA[nxt][4]=a1.x; rA[nxt][5]=a1.y; rA[nxt][6]=a1.z; rA[nxt][7]=a1.w;
                rB[nxt][0]=b0.x; rB[nxt][1]=b0.y; rB[nxt][2]=b0.z; rB[nxt][3]=b0.w;
                rB[nxt][4]=b1.x; rB[nxt][5]=b1.y; rB[nxt][6]=b1.z; rB[nxt][7]=b1.w;
            }
#pragma unroll
            for (int i = 0; i < 8; i++)
#pragma unroll
                for (int j = 0; j < 8; j++)
                    acc[i][j] = fmaf(rA[cur][i], rB[cur][j], acc[i][j]);
        }

        // ---- store next tile into the other buffer; single barrier ----
        if (has_next) {
#pragma unroll
            for (int t = 0; t < 8; t++) As[buf ^ 1][a_kk][a_mrow + t * 16] = pa[t];
#pragma unroll
            for (int t = 0; t < 8; t++) Bs[buf ^ 1][b_krow + t * 2][b_nn] = pb[t];
            __syncthreads();
        }
    }

#pragma unroll
    for (int i = 0; i < 8; i++) {
        int m = m0 + ty * 8 + i;
#pragma unroll
        for (int j = 0; j < 8; j++) {
            int n = n0 + tx * 8 + j;
            if (n < N) {
                float v = acc[i][j];
                if (EPI == 1) v += bias[n];
                if (EPI == 2) v = fmaxf(v + bias[n], 0.f) + epi_add[(size_t)m * N + n];
                C[(size_t)m * N + n] = v;
            }
        }
    }
}

// ---------------- deformable bilinear sampling ------------------------------------
// thread -> (m, k, g); writes 32 contiguous channels of g_sampled[m][k][g*32..]
__global__ void sample_kernel() {
    int idx = blockIdx.x * blockDim.x + threadIdx.x;   // [0, 16384*72)
    if (idx >= MTOT * 9 * GRP) return;
    int g  = idx & 7;
    int mk = idx >> 3;
    int k  = mk % 9;
    int m  = mk / 9;
    int b = m >> 12, y = (m >> 6) & 63, x = m & 63;

    const float* omp = g_om + (size_t)m * NOM;
    float dy = omp[g * 18 + k * 2];
    float dx = omp[g * 18 + k * 2 + 1];
    float mask = 1.0f / (1.0f + expf(-omp[144 + g * 9 + k]));

    float sy = (float)y + (float)(k / 3 - 1) + dy;
    float sx = (float)x + (float)(k % 3 - 1) + dx;
    float y0f = floorf(sy), x0f = floorf(sx);
    float wy = sy - y0f, wx = sx - x0f;

    float vy0 = (y0f >= 0.f && y0f <= 63.f) ? 1.f : 0.f;
    float vy1 = (y0f + 1.f >= 0.f && y0f + 1.f <= 63.f) ? 1.f : 0.f;
    float vx0 = (x0f >= 0.f && x0f <= 63.f) ? 1.f : 0.f;
    float vx1 = (x0f + 1.f >= 0.f && x0f + 1.f <= 63.f) ? 1.f : 0.f;

    int yc0 = (int)fminf(fmaxf(y0f, 0.f), 63.f);
    int yc1 = (int)fminf(fmaxf(y0f + 1.f, 0.f), 63.f);
    int xc0 = (int)fminf(fmaxf(x0f, 0.f), 63.f);
    int xc1 = (int)fminf(fmaxf(x0f + 1.f, 0.f), 63.f);

    float w00 = (1 - wy) * (1 - wx) * vy0 * vx0 * mask;
    float w01 = (1 - wy) * wx       * vy0 * vx1 * mask;
    float w10 = wy       * (1 - wx) * vy1 * vx0 * mask;
    float w11 = wy       * wx       * vy1 * vx1 * mask;

    int plane = (b << 12);
    const float4* p00 = (const float4*)(g_coarse_up + ((plane + (yc0 << 6) + xc0) * CC) + g * CG);
    const float4* p01 = (const float4*)(g_coarse_up + ((plane + (yc0 << 6) + xc1) * CC) + g * CG);
    const float4* p10 = (const float4*)(g_coarse_up + ((plane + (yc1 << 6) + xc0) * CC) + g * CG);
    const float4* p11 = (const float4*)(g_coarse_up + ((plane + (yc1 << 6) + xc1) * CC) + g * CG);

    float4* dst = (float4*)(g_sampled + (size_t)(m * 9 + k) * CC + g * CG);
#pragma unroll
    for (int i = 0; i < 8; i++) {
        float4 a = p00[i], bb = p01[i], c = p10[i], d = p11[i];
        float4 r;
        r.x = w00*a.x + w01*bb.x + w10*c.x + w11*d.x;
        r.y = w00*a.y + w01*bb.y + w10*c.y + w11*d.y;
        r.z = w00*a.z + w01*bb.z + w10*c.z + w11*d.z;
        r.w = w00*a.w + w01*bb.w + w10*c.w + w11*d.w;
        dst[i] = r;
    }
}

// ---------------- launch --------------------------------------------------------
extern "C" void kernel_launch(void* const* d_in, const int* in_sizes, int n_in,
                              void* d_out, int out_size) {
    const float* coarse = (const float*)d_in[0];
    const float* fine   = (const float*)d_in[1];
    const float* w_att  = (const float*)d_in[2];
    const float* w_sel  = (const float*)d_in[3];
    const float* w_off  = (const float*)d_in[4];
    const float* w_om   = (const float*)d_in[5];
    const float* b_om   = (const float*)d_in[6];
    const float* w_dcn  = (const float*)d_in[7];
    const float* b_dcn  = (const float*)d_in[8];
    float* out = (float*)d_out;

    float *cu, *fcal, *alg, *om, *samp, *attn;
    cudaGetSymbolAddress((void**)&cu,   g_coarse_up);
    cudaGetSymbolAddress((void**)&fcal, g_fine_cal);
    cudaGetSymbolAddress((void**)&alg,  g_align);
    cudaGetSymbolAddress((void**)&om,   g_om);
    cudaGetSymbolAddress((void**)&samp, g_sampled);
    cudaGetSymbolAddress((void**)&attn, g_attn_p1);

    upsample_kernel<<<(BB*HH*WW*CC/4 + 255)/256, 256>>>(coarse);
    pool_part_kernel<<<64, 256>>>(fine);
    attn_kernel<<<BB, 256>>>(w_att);

    // fine_cal = (fine * (attn+1)) @ w_sel
    gemm_kernel<1,0><<<dim3(2,128), 256>>>(nullptr, w_sel, fcal,
        MTOT, CC, CC, fine, attn, nullptr, nullptr);

    // align = concat(fine_cal, 2*coarse_up) @ w_off
    gemm_kernel<2,0><<<dim3(4,128), 256>>>(nullptr, w_off, alg,
        MTOT, CF2, CF2, fcal, cu, nullptr, nullptr);

    // om = conv3x3(align, w_om) + b_om   (im2col-fused)
    gemm_kernel<3,1><<<dim3(2,128), 256>>>(nullptr, w_om, om,
        MTOT, NOM, KIM, alg, nullptr, b_om, nullptr);

    // deformable sampling -> g_sampled [16384, 9*256]
    sample_kernel<<<(MTOT*9*GRP + 255)/256, 256>>>();

    // out = relu(sampled @ w_dcn + b_dcn) + fine_cal
    gemm_kernel<0,2><<<dim3(2,128), 256>>>(samp, w_dcn, out,
        MTOT, CC, KDCN, nullptr, nullptr, b_dcn, fcal);
}